// round 13
// baseline (speedup 1.0000x reference)
#include <cuda_runtime.h>

#define NG    4096
#define WI    96
#define HI    96
#define NPIX  (WI*HI)
#define TS    8
#define TGX   (WI/TS)         // 12
#define TGY   (HI/TS)         // 12
#define NTILE (TGX*TGY)       // 144
#define NWORD (NG/32)         // 128 mask words per tile
#define NSEG  16              // depth segments per tile
#define RTHR  (NSEG*64)       // raster threads per block = 1024
#define PBLK  128             // preprocess blocks
#define PTHR  128             // preprocess threads per block
#define PGPB  (NG/PBLK)       // 32 gaussians per preprocess block

// ---- device scratch ----
__device__ __align__(16) float g_depth[NG];
__device__ float4   g_pre0[NG];    // ux, uy, cinv0, cinv1
__device__ float4   g_pre1[NG];    // cinv2, alpha, R, G
__device__ float    g_preB[NG];    // B
__device__ float4   g_prebb[NG];   // xmin, xmax, ymin, ymax
__device__ float4   g_s0[NG];
__device__ float4   g_s1[NG];
__device__ float    g_sB[NG];
__device__ unsigned g_tilemask[NTILE * NWORD];

// ============================================================
// Kernel 1: per-gaussian preprocessing (+ tile mask zeroing)
// Coalesced cooperative staging: 128 threads stream 32
// gaussians' inputs into shared as contiguous transactions,
// then 32 threads compute from shared.
// ============================================================
__global__ void __launch_bounds__(PTHR) preprocess_kernel(
    const float* __restrict__ pws,
    const float* __restrict__ low_shs,
    const float* __restrict__ high_shs,
    const float* __restrict__ alphas_raw,
    const float* __restrict__ scales_raw,
    const float* __restrict__ rots_raw,
    const float* __restrict__ Rcw,
    const float* __restrict__ tcw,
    const float* __restrict__ cam,
    float* __restrict__ areas, int write_areas)
{
    __shared__ float s_sh [PGPB*45];
    __shared__ float s_pws[PGPB*3];
    __shared__ float s_lsh[PGPB*3];
    __shared__ float s_sc [PGPB*3];
    __shared__ float s_al [PGPB];

    int tid   = threadIdx.x;
    int bid   = blockIdx.x;
    int gbase = bid * PGPB;

    // zero tile bitmasks (18432 words over 16384 threads)
    for (int k = bid * PTHR + tid; k < NTILE * NWORD; k += PBLK * PTHR)
        g_tilemask[k] = 0u;

    // ---- coalesced staging ----
    #pragma unroll
    for (int k = tid; k < PGPB*45; k += PTHR) s_sh[k]  = high_shs[gbase*45 + k];
    if (tid < PGPB*3)  s_pws[tid] = pws[gbase*3 + tid];
    else if (tid < PGPB*3 + 32) { int t = tid - PGPB*3; s_al[t] = alphas_raw[gbase + t]; }
    {
        int k = tid;
        if (k < PGPB*3) s_lsh[k] = low_shs[gbase*3 + k];
        if (k < PGPB*3) s_sc[k]  = scales_raw[gbase*3 + k];
    }
    __syncthreads();

    if (tid < PGPB) {
        int i = gbase + tid;

        float fx = cam[0], fy = cam[1], cx = cam[2], cy = cam[3];
        float R00=Rcw[0],R01=Rcw[1],R02=Rcw[2];
        float R10=Rcw[3],R11=Rcw[4],R12=Rcw[5];
        float R20=Rcw[6],R21=Rcw[7],R22=Rcw[8];
        float t0=tcw[0], t1=tcw[1], t2=tcw[2];

        float pwx = s_pws[tid*3+0], pwy = s_pws[tid*3+1], pwz = s_pws[tid*3+2];
        float4 q4 = ((const float4*)rots_raw)[i];   // 16B-aligned, one lane each

        float pcx = R00*pwx + R01*pwy + R02*pwz + t0;
        float pcy = R10*pwx + R11*pwy + R12*pwz + t1;
        float pcz = R20*pwx + R21*pwy + R22*pwz + t2;
        float depth = pcz;
        float zs = depth > 1e-6f ? depth : 1e-6f;
        float invz = 1.0f / zs;

        float ux = fx * pcx * invz + cx;
        float uy = fy * pcy * invz + cy;

        float qw = q4.x, qx = q4.y, qy = q4.z, qz = q4.w;
        float qn = rsqrtf(qw*qw + qx*qx + qy*qy + qz*qz);
        qw*=qn; qx*=qn; qy*=qn; qz*=qn;

        float s0 = expf(s_sc[tid*3+0]);
        float s1 = expf(s_sc[tid*3+1]);
        float s2 = expf(s_sc[tid*3+2]);

        float r00 = 1.f - 2.f*(qy*qy + qz*qz), r01 = 2.f*(qx*qy - qw*qz), r02 = 2.f*(qx*qz + qw*qy);
        float r10 = 2.f*(qx*qy + qw*qz), r11 = 1.f - 2.f*(qx*qx + qz*qz), r12 = 2.f*(qy*qz - qw*qx);
        float r20 = 2.f*(qx*qz - qw*qy), r21 = 2.f*(qy*qz + qw*qx), r22 = 1.f - 2.f*(qx*qx + qy*qy);

        float m00=r00*s0, m01=r01*s1, m02=r02*s2;
        float m10=r10*s0, m11=r11*s1, m12=r12*s2;
        float m20=r20*s0, m21=r21*s1, m22=r22*s2;

        float limx = 1.3f * ((float)WI / (2.0f*fx));
        float limy = 1.3f * ((float)HI / (2.0f*fy));
        float txc = fminf(fmaxf(pcx*invz, -limx), limx) * zs;
        float tyc = fminf(fmaxf(pcy*invz, -limy), limy) * zs;
        float j00 = fx*invz,  j02 = -fx*txc*invz*invz;
        float j11 = fy*invz,  j12 = -fy*tyc*invz*invz;

        float T00 = j00*R00 + j02*R20, T01 = j00*R01 + j02*R21, T02 = j00*R02 + j02*R22;
        float T10 = j11*R10 + j12*R20, T11 = j11*R11 + j12*R21, T12 = j11*R12 + j12*R22;

        float W00 = T00*m00 + T01*m10 + T02*m20;
        float W01 = T00*m01 + T01*m11 + T02*m21;
        float W02 = T00*m02 + T01*m12 + T02*m22;
        float W10 = T10*m00 + T11*m10 + T12*m20;
        float W11 = T10*m01 + T11*m11 + T12*m21;
        float W12 = T10*m02 + T11*m12 + T12*m22;

        float a  = W00*W00 + W01*W01 + W02*W02 + 0.3f;
        float b  = W00*W10 + W01*W11 + W02*W12;
        float cc = W10*W10 + W11*W11 + W12*W12 + 0.3f;
        float det = a*cc - b*b;
        float inv = 1.0f / det;

        float mid = 0.5f*(a + cc);
        float lam = mid + sqrtf(fmaxf(mid*mid - det, 0.1f));
        float radius = ceilf(3.0f * sqrtf(lam));

        float alpha = 1.0f / (1.0f + expf(-s_al[tid]));
        if (!(depth > 0.2f)) alpha = 0.0f;

        float twx = -(R00*t0 + R10*t1 + R20*t2);
        float twy = -(R01*t0 + R11*t1 + R21*t2);
        float twz = -(R02*t0 + R12*t1 + R22*t2);
        float dx = pwx - twx, dy = pwy - twy, dz = pwz - twz;
        float dn = rsqrtf(dx*dx + dy*dy + dz*dz);
        float x = dx*dn, y = dy*dn, z = dz*dn;
        float xx = x*x, yy = y*y, zz = z*z;
        float xy = x*y, yz = y*z, xz = x*z;

        float B[16];
        B[0]  = 0.28209479177387814f;
        B[1]  = -0.4886025119029199f * y;
        B[2]  =  0.4886025119029199f * z;
        B[3]  = -0.4886025119029199f * x;
        B[4]  =  1.0925484305920792f * xy;
        B[5]  = -1.0925484305920792f * yz;
        B[6]  =  0.31539156525252005f * (2.f*zz - xx - yy);
        B[7]  = -1.0925484305920792f * xz;
        B[8]  =  0.5462742152960396f * (xx - yy);
        B[9]  = -0.5900435899266435f * y * (3.f*xx - yy);
        B[10] =  2.890611442640554f  * xy * z;
        B[11] = -0.4570457994644658f * y * (4.f*zz - xx - yy);
        B[12] =  0.3731763325901154f * z * (2.f*zz - 3.f*xx - 3.f*yy);
        B[13] = -0.4570457994644658f * x * (4.f*zz - xx - yy);
        B[14] =  1.445305721320277f  * z * (xx - yy);
        B[15] = -0.5900435899266435f * x * (xx - 3.f*yy);

        float col[3];
        #pragma unroll
        for (int c = 0; c < 3; c++) {
            float v = B[0] * s_lsh[tid*3 + c];
            #pragma unroll
            for (int j = 1; j < 16; j++)
                v += B[j] * s_sh[tid*45 + 3*(j-1) + c];
            col[c] = fmaxf(v + 0.5f, 0.0f);
        }

        // exact cull bbox
        float4 bb;
        if (alpha * 255.0f <= 1.0f) {
            bb = make_float4(1e9f, -1e9f, 1e9f, -1e9f);
        } else {
            float qcut = 2.0f * logf(255.0f * alpha) * 1.0001f;
            float ex = sqrtf(qcut * a);
            float ey = sqrtf(qcut * cc);
            bb = make_float4(ux - ex, ux + ex, uy - ey, uy + ey);
        }

        g_depth[i] = depth;
        g_pre0[i] = make_float4(ux, uy, cc*inv, -b*inv);
        g_pre1[i] = make_float4(a*inv, alpha, col[0], col[1]);
        g_preB[i] = col[2];
        g_prebb[i] = bb;

        if (write_areas) {
            areas[2*i+0] = radius;
            areas[2*i+1] = radius;
        }
    }
}

// ============================================================
// Kernel 2: stable rank sort — 128 blocks x 1024 threads,
// 32 gaussians per block (1 per warp); depth staged once
// per block via float4 (single pass, 1024 lanes).
// ============================================================
__global__ void __launch_bounds__(1024) rank_scatter_kernel()
{
    __shared__ __align__(16) float s_d[NG];
    int tid  = threadIdx.x;
    int lane = tid & 31;
    int wrp  = tid >> 5;
    int i    = blockIdx.x * 32 + wrp;

    {
        const float4* dp = (const float4*)g_depth;
        float4* sp = (float4*)s_d;
        sp[tid] = dp[tid];                       // NG/4 == 1024
    }
    __syncthreads();

    float di = s_d[i];
    int cnt = 0;
    #pragma unroll 4
    for (int j = lane; j < NG; j += 32) {
        float dj = s_d[j];
        cnt += (dj < di) || (dj == di && j < i);
    }
    #pragma unroll
    for (int d = 16; d > 0; d >>= 1)
        cnt += __shfl_xor_sync(0xffffffffu, cnt, d);
    int r = cnt;

    if      (lane == 0) g_s0[r] = g_pre0[i];
    else if (lane == 1) g_s1[r] = g_pre1[i];
    else if (lane == 2) g_sB[r] = g_preB[i];
    else if (lane == 3) {
        float4 bb = g_prebb[i];
        int txlo = max(0,     (int)floorf((bb.x - 7.0f) * 0.125f));
        int txhi = min(TGX-1, (int)floorf( bb.y          * 0.125f + 0.001f));
        int tylo = max(0,     (int)floorf((bb.z - 7.0f) * 0.125f));
        int tyhi = min(TGY-1, (int)floorf( bb.w          * 0.125f + 0.001f));
        unsigned bit = 1u << (r & 31);
        int word = r >> 5;
        if (txlo <= txhi)
            for (int ty = tylo; ty <= tyhi; ty++)
                for (int tx = txlo; tx <= txhi; tx++)
                    atomicOr(&g_tilemask[(ty*TGX + tx) * NWORD + word], bit);
    }
}

// ============================================================
// Kernel 3: tiled rasterizer — 1024 threads per 8x8 tile.
// 16 depth segments x 64 pixel-threads; 1024-wide staging
// rounds (typically ONE); ordered composition.
// s_col aliases s_f0 (only live after the final blend sync).
// ============================================================
__global__ void __launch_bounds__(RTHR, 1) raster_kernel(float* __restrict__ img)
{
    __shared__ unsigned short s_idx[NG];       // 8 KB
    __shared__ float4 s_f0[RTHR];              // 16 KB (aliased by s_col)
    __shared__ float4 s_f1[RTHR];              // 16 KB
    __shared__ float  s_Bc[RTHR];              // 4 KB
    __shared__ int    s_wtot[4];

    float4* s_col = s_f0;                      // alias

    int tid  = threadIdx.x;
    int lane = tid & 31;
    int wrp  = tid >> 5;
    int tile = blockIdx.x;
    int tx0  = (tile % TGX) * TS;
    int ty0  = (tile / TGX) * TS;

    // ---- expand tile bitmask -> ordered survivor list (first 128 threads) ----
    const unsigned* mask = &g_tilemask[tile * NWORD];
    unsigned w0 = 0; int c = 0;
    if (tid < NWORD) { w0 = mask[tid]; c = __popc(w0); }

    int incl = c;
    #pragma unroll
    for (int d = 1; d < 32; d <<= 1) {
        int o = __shfl_up_sync(0xffffffffu, incl, d);
        if (lane >= d) incl += o;
    }
    if (wrp < 4 && lane == 31) s_wtot[wrp] = incl;
    __syncthreads();
    int n = s_wtot[0] + s_wtot[1] + s_wtot[2] + s_wtot[3];
    if (tid < NWORD) {
        int off = incl - c;
        #pragma unroll
        for (int k = 0; k < 4; k++) if (wrp > k) off += s_wtot[k];
        int gb = tid * 32;
        unsigned w = w0;
        while (w) { int b = __ffs(w) - 1; w &= w - 1; s_idx[off++] = (unsigned short)(gb + b); }
    }
    __syncthreads();

    // ---- segmented blend ----
    int seg = tid >> 6;          // 0..15
    int sp  = tid & 63;          // pixel within tile
    float px = (float)(tx0 + (sp & 7));
    float py = (float)(ty0 + (sp >> 3));

    int nq = (n + NSEG - 1) / NSEG;
    int s_begin = seg * nq;
    int s_end   = min(n, s_begin + nq);
    int nbatch  = (nq + 63) >> 6;

    float T = 1.0f;
    float cr = 0.f, cg = 0.f, cb = 0.f;

    for (int b = 0; b < nbatch; b++) {
        int idx = s_begin + b * 64 + sp;
        if (idx < s_end) {
            int g = s_idx[idx];
            s_f0[tid] = g_s0[g];
            s_f1[tid] = g_s1[g];
            s_Bc[tid] = g_sB[g];
        }
        __syncthreads();

        int nb = s_end - (s_begin + b * 64);
        if (nb > 64) nb = 64;
        if (nb > 0 && T > 1e-4f) {
            int base = seg * 64;
            #pragma unroll 2
            for (int j = 0; j < nb; j++) {
                float4 f0 = s_f0[base + j];
                float4 f1 = s_f1[base + j];
                float dx = f0.x - px, dy = f0.y - py;
                float power = -0.5f * (f0.z*dx*dx + f1.x*dy*dy) - f0.w*dx*dy;
                float ap = f1.y * __expf(fminf(power, 0.0f));
                ap = fminf(ap, 0.99f);
                if (ap >= (1.0f/255.0f)) {
                    float wgt = (T > 1e-4f) ? ap * T : 0.0f;
                    cr += wgt * f1.z;
                    cg += wgt * f1.w;
                    cb += wgt * s_Bc[base + j];
                    T *= (1.0f - ap);
                }
            }
        }
        __syncthreads();
    }

    // ---- ordered composition across the 16 segments ----
    s_col[tid] = make_float4(cr, cg, cb, T);
    __syncthreads();

    if (tid < 64) {
        float Cr = 0.f, Cg = 0.f, Cb = 0.f;
        #pragma unroll
        for (int k = NSEG - 1; k >= 0; k--) {
            float4 a = s_col[k * 64 + sp];
            Cr = a.x + a.w * Cr;
            Cg = a.y + a.w * Cg;
            Cb = a.z + a.w * Cb;
        }
        int pix = (ty0 + (sp >> 3)) * WI + (tx0 + (sp & 7));
        img[0*NPIX + pix] = Cr;
        img[1*NPIX + pix] = Cg;
        img[2*NPIX + pix] = Cb;
    }
}

// ============================================================
extern "C" void kernel_launch(void* const* d_in, const int* in_sizes, int n_in,
                              void* d_out, int out_size)
{
    const float* pws        = (const float*)d_in[0];
    const float* low_shs    = (const float*)d_in[1];
    const float* high_shs   = (const float*)d_in[2];
    const float* alphas_raw = (const float*)d_in[3];
    const float* scales_raw = (const float*)d_in[4];
    const float* rots_raw   = (const float*)d_in[5];
    // d_in[6] = us (unused)
    const float* Rcw        = (const float*)d_in[7];
    const float* tcw        = (const float*)d_in[8];
    const float* cam        = (const float*)d_in[9];

    float* out   = (float*)d_out;
    int write_areas = (out_size >= 3*NPIX + 2*NG) ? 1 : 0;
    float* areas = out + 3*NPIX;

    preprocess_kernel<<<PBLK, PTHR>>>(pws, low_shs, high_shs, alphas_raw,
                                      scales_raw, rots_raw, Rcw, tcw, cam,
                                      areas, write_areas);
    rank_scatter_kernel<<<NG/32, 1024>>>();
    raster_kernel<<<NTILE, RTHR>>>(out);
}

// round 14
// speedup vs baseline: 1.3878x; 1.3878x over previous
#include <cuda_runtime.h>

#define NG    4096
#define WI    96
#define HI    96
#define NPIX  (WI*HI)
#define TS    8
#define TGX   (WI/TS)         // 12
#define TGY   (HI/TS)         // 12
#define NTILE (TGX*TGY)       // 144
#define NWORD (NG/32)         // 128 mask words per tile
#define NSEG  16              // depth segments per tile
#define RTHR  (NSEG*64)       // raster threads per block = 1024

// ---- device scratch ----
__device__ __align__(16) float g_depth[NG];
__device__ float4   g_pre0[NG];    // ux, uy, cinv0, cinv1
__device__ float4   g_pre1[NG];    // cinv2, alpha, R, G
__device__ float    g_preB[NG];    // B
__device__ float4   g_prebb[NG];   // xmin, xmax, ymin, ymax
__device__ float4   g_s0[NG];
__device__ float4   g_s1[NG];
__device__ float    g_sB[NG];
__device__ unsigned g_tilemask[NTILE * NWORD];

// ============================================================
// Kernel 1: per-gaussian preprocessing (+ tile mask zeroing)
// R12 configuration: 128 blocks x 32 threads, front-loaded
// register reads for maximum per-warp MLP, ~128 SMs fetching.
// ============================================================
__global__ void __launch_bounds__(32) preprocess_kernel(
    const float* __restrict__ pws,
    const float* __restrict__ low_shs,
    const float* __restrict__ high_shs,
    const float* __restrict__ alphas_raw,
    const float* __restrict__ scales_raw,
    const float* __restrict__ rots_raw,
    const float* __restrict__ Rcw,
    const float* __restrict__ tcw,
    const float* __restrict__ cam,
    float* __restrict__ areas, int write_areas)
{
    int i = blockIdx.x * blockDim.x + threadIdx.x;
    if (i >= NG) return;

    for (int k = i; k < NTILE * NWORD; k += NG) g_tilemask[k] = 0u;

    // ---------- front-loaded input reads (maximize outstanding loads) ----------
    float pwx = pws[3*i+0], pwy = pws[3*i+1], pwz = pws[3*i+2];
    float4 q4 = ((const float4*)rots_raw)[i];
    float sc0 = scales_raw[3*i+0], sc1 = scales_raw[3*i+1], sc2 = scales_raw[3*i+2];
    float araw = alphas_raw[i];
    float lsh0 = low_shs[3*i+0], lsh1 = low_shs[3*i+1], lsh2 = low_shs[3*i+2];
    float sh[45];
    #pragma unroll
    for (int v = 0; v < 45; v++) sh[v] = high_shs[45*i + v];

    float fx = cam[0], fy = cam[1], cx = cam[2], cy = cam[3];
    float R00=Rcw[0],R01=Rcw[1],R02=Rcw[2];
    float R10=Rcw[3],R11=Rcw[4],R12=Rcw[5];
    float R20=Rcw[6],R21=Rcw[7],R22=Rcw[8];
    float t0=tcw[0], t1=tcw[1], t2=tcw[2];

    // ---------- compute ----------
    float pcx = R00*pwx + R01*pwy + R02*pwz + t0;
    float pcy = R10*pwx + R11*pwy + R12*pwz + t1;
    float pcz = R20*pwx + R21*pwy + R22*pwz + t2;
    float depth = pcz;
    float zs = depth > 1e-6f ? depth : 1e-6f;
    float invz = 1.0f / zs;

    float ux = fx * pcx * invz + cx;
    float uy = fy * pcy * invz + cy;

    float qw = q4.x, qx = q4.y, qy = q4.z, qz = q4.w;
    float qn = rsqrtf(qw*qw + qx*qx + qy*qy + qz*qz);
    qw*=qn; qx*=qn; qy*=qn; qz*=qn;

    float s0 = expf(sc0);
    float s1 = expf(sc1);
    float s2 = expf(sc2);

    float r00 = 1.f - 2.f*(qy*qy + qz*qz), r01 = 2.f*(qx*qy - qw*qz), r02 = 2.f*(qx*qz + qw*qy);
    float r10 = 2.f*(qx*qy + qw*qz), r11 = 1.f - 2.f*(qx*qx + qz*qz), r12 = 2.f*(qy*qz - qw*qx);
    float r20 = 2.f*(qx*qz - qw*qy), r21 = 2.f*(qy*qz + qw*qx), r22 = 1.f - 2.f*(qx*qx + qy*qy);

    float m00=r00*s0, m01=r01*s1, m02=r02*s2;
    float m10=r10*s0, m11=r11*s1, m12=r12*s2;
    float m20=r20*s0, m21=r21*s1, m22=r22*s2;

    float limx = 1.3f * ((float)WI / (2.0f*fx));
    float limy = 1.3f * ((float)HI / (2.0f*fy));
    float txc = fminf(fmaxf(pcx*invz, -limx), limx) * zs;
    float tyc = fminf(fmaxf(pcy*invz, -limy), limy) * zs;
    float j00 = fx*invz,  j02 = -fx*txc*invz*invz;
    float j11 = fy*invz,  j12 = -fy*tyc*invz*invz;

    float T00 = j00*R00 + j02*R20, T01 = j00*R01 + j02*R21, T02 = j00*R02 + j02*R22;
    float T10 = j11*R10 + j12*R20, T11 = j11*R11 + j12*R21, T12 = j11*R12 + j12*R22;

    float W00 = T00*m00 + T01*m10 + T02*m20;
    float W01 = T00*m01 + T01*m11 + T02*m21;
    float W02 = T00*m02 + T01*m12 + T02*m22;
    float W10 = T10*m00 + T11*m10 + T12*m20;
    float W11 = T10*m01 + T11*m11 + T12*m21;
    float W12 = T10*m02 + T11*m12 + T12*m22;

    float a  = W00*W00 + W01*W01 + W02*W02 + 0.3f;
    float b  = W00*W10 + W01*W11 + W02*W12;
    float cc = W10*W10 + W11*W11 + W12*W12 + 0.3f;
    float det = a*cc - b*b;
    float inv = 1.0f / det;

    float mid = 0.5f*(a + cc);
    float lam = mid + sqrtf(fmaxf(mid*mid - det, 0.1f));
    float radius = ceilf(3.0f * sqrtf(lam));

    float alpha = 1.0f / (1.0f + expf(-araw));
    if (!(depth > 0.2f)) alpha = 0.0f;

    float twx = -(R00*t0 + R10*t1 + R20*t2);
    float twy = -(R01*t0 + R11*t1 + R21*t2);
    float twz = -(R02*t0 + R12*t1 + R22*t2);
    float dx = pwx - twx, dy = pwy - twy, dz = pwz - twz;
    float dn = rsqrtf(dx*dx + dy*dy + dz*dz);
    float x = dx*dn, y = dy*dn, z = dz*dn;
    float xx = x*x, yy = y*y, zz = z*z;
    float xy = x*y, yz = y*z, xz = x*z;

    float B[16];
    B[0]  = 0.28209479177387814f;
    B[1]  = -0.4886025119029199f * y;
    B[2]  =  0.4886025119029199f * z;
    B[3]  = -0.4886025119029199f * x;
    B[4]  =  1.0925484305920792f * xy;
    B[5]  = -1.0925484305920792f * yz;
    B[6]  =  0.31539156525252005f * (2.f*zz - xx - yy);
    B[7]  = -1.0925484305920792f * xz;
    B[8]  =  0.5462742152960396f * (xx - yy);
    B[9]  = -0.5900435899266435f * y * (3.f*xx - yy);
    B[10] =  2.890611442640554f  * xy * z;
    B[11] = -0.4570457994644658f * y * (4.f*zz - xx - yy);
    B[12] =  0.3731763325901154f * z * (2.f*zz - 3.f*xx - 3.f*yy);
    B[13] = -0.4570457994644658f * x * (4.f*zz - xx - yy);
    B[14] =  1.445305721320277f  * z * (xx - yy);
    B[15] = -0.5900435899266435f * x * (xx - 3.f*yy);

    float col[3];
    float lsh[3] = {lsh0, lsh1, lsh2};
    #pragma unroll
    for (int c = 0; c < 3; c++) {
        float v = B[0] * lsh[c];
        #pragma unroll
        for (int j = 1; j < 16; j++)
            v += B[j] * sh[3*(j-1) + c];
        col[c] = fmaxf(v + 0.5f, 0.0f);
    }

    // exact cull bbox: ap = alpha*exp(-q/2) >= 1/255 requires q <= 2 ln(255 alpha)
    float4 bb;
    if (alpha * 255.0f <= 1.0f) {
        bb = make_float4(1e9f, -1e9f, 1e9f, -1e9f);
    } else {
        float qcut = 2.0f * logf(255.0f * alpha) * 1.0001f;
        float ex = sqrtf(qcut * a);
        float ey = sqrtf(qcut * cc);
        bb = make_float4(ux - ex, ux + ex, uy - ey, uy + ey);
    }

    g_depth[i] = depth;
    g_pre0[i] = make_float4(ux, uy, cc*inv, -b*inv);
    g_pre1[i] = make_float4(a*inv, alpha, col[0], col[1]);
    g_preB[i] = col[2];
    g_prebb[i] = bb;

    if (write_areas) {
        ((float2*)areas)[i] = make_float2(radius, radius);
    }
}

// ============================================================
// Kernel 2: stable rank sort — 128 blocks x 1024 threads,
// 32 gaussians per block (1 per warp); depth staged once
// per block via float4 (single pass, 1024 lanes).
// ============================================================
__global__ void __launch_bounds__(1024) rank_scatter_kernel()
{
    __shared__ __align__(16) float s_d[NG];
    int tid  = threadIdx.x;
    int lane = tid & 31;
    int wrp  = tid >> 5;
    int i    = blockIdx.x * 32 + wrp;

    {
        const float4* dp = (const float4*)g_depth;
        float4* sp = (float4*)s_d;
        sp[tid] = dp[tid];                       // NG/4 == 1024
    }
    __syncthreads();

    float di = s_d[i];
    int cnt = 0;
    #pragma unroll 8
    for (int j = lane; j < NG; j += 32) {
        float dj = s_d[j];
        cnt += (dj < di) || (dj == di && j < i);
    }
    #pragma unroll
    for (int d = 16; d > 0; d >>= 1)
        cnt += __shfl_xor_sync(0xffffffffu, cnt, d);
    int r = cnt;

    if      (lane == 0) g_s0[r] = g_pre0[i];
    else if (lane == 1) g_s1[r] = g_pre1[i];
    else if (lane == 2) g_sB[r] = g_preB[i];
    else if (lane == 3) {
        float4 bb = g_prebb[i];
        int txlo = max(0,     (int)floorf((bb.x - 7.0f) * 0.125f));
        int txhi = min(TGX-1, (int)floorf( bb.y          * 0.125f + 0.001f));
        int tylo = max(0,     (int)floorf((bb.z - 7.0f) * 0.125f));
        int tyhi = min(TGY-1, (int)floorf( bb.w          * 0.125f + 0.001f));
        unsigned bit = 1u << (r & 31);
        int word = r >> 5;
        if (txlo <= txhi)
            for (int ty = tylo; ty <= tyhi; ty++)
                for (int tx = txlo; tx <= txhi; tx++)
                    atomicOr(&g_tilemask[(ty*TGX + tx) * NWORD + word], bit);
    }
}

// ============================================================
// Kernel 3: tiled rasterizer — 1024 threads per 8x8 tile.
// 16 depth segments x 64 pixel-threads; 1024-wide staging
// rounds (typically ONE); ordered composition.
// s_col aliases s_f0 (only live after the final blend sync).
// ============================================================
__global__ void __launch_bounds__(RTHR, 1) raster_kernel(float* __restrict__ img)
{
    __shared__ unsigned short s_idx[NG];       // 8 KB
    __shared__ float4 s_f0[RTHR];              // 16 KB (aliased by s_col)
    __shared__ float4 s_f1[RTHR];              // 16 KB
    __shared__ float  s_Bc[RTHR];              // 4 KB
    __shared__ int    s_wtot[4];

    float4* s_col = s_f0;                      // alias

    int tid  = threadIdx.x;
    int lane = tid & 31;
    int wrp  = tid >> 5;
    int tile = blockIdx.x;
    int tx0  = (tile % TGX) * TS;
    int ty0  = (tile / TGX) * TS;

    // ---- expand tile bitmask -> ordered survivor list (first 128 threads) ----
    const unsigned* mask = &g_tilemask[tile * NWORD];
    unsigned w0 = 0; int c = 0;
    if (tid < NWORD) { w0 = mask[tid]; c = __popc(w0); }

    int incl = c;
    #pragma unroll
    for (int d = 1; d < 32; d <<= 1) {
        int o = __shfl_up_sync(0xffffffffu, incl, d);
        if (lane >= d) incl += o;
    }
    if (wrp < 4 && lane == 31) s_wtot[wrp] = incl;
    __syncthreads();
    int n = s_wtot[0] + s_wtot[1] + s_wtot[2] + s_wtot[3];
    if (tid < NWORD) {
        int off = incl - c;
        #pragma unroll
        for (int k = 0; k < 4; k++) if (wrp > k) off += s_wtot[k];
        int gb = tid * 32;
        unsigned w = w0;
        while (w) { int b = __ffs(w) - 1; w &= w - 1; s_idx[off++] = (unsigned short)(gb + b); }
    }
    __syncthreads();

    // ---- segmented blend ----
    int seg = tid >> 6;          // 0..15
    int sp  = tid & 63;          // pixel within tile
    float px = (float)(tx0 + (sp & 7));
    float py = (float)(ty0 + (sp >> 3));

    int nq = (n + NSEG - 1) / NSEG;
    int s_begin = seg * nq;
    int s_end   = min(n, s_begin + nq);
    int nbatch  = (nq + 63) >> 6;

    float T = 1.0f;
    float cr = 0.f, cg = 0.f, cb = 0.f;

    for (int b = 0; b < nbatch; b++) {
        int idx = s_begin + b * 64 + sp;
        if (idx < s_end) {
            int g = s_idx[idx];
            s_f0[tid] = g_s0[g];
            s_f1[tid] = g_s1[g];
            s_Bc[tid] = g_sB[g];
        }
        __syncthreads();

        int nb = s_end - (s_begin + b * 64);
        if (nb > 64) nb = 64;
        if (nb > 0 && T > 1e-4f) {
            int base = seg * 64;
            #pragma unroll 2
            for (int j = 0; j < nb; j++) {
                float4 f0 = s_f0[base + j];
                float4 f1 = s_f1[base + j];
                float dx = f0.x - px, dy = f0.y - py;
                float power = -0.5f * (f0.z*dx*dx + f1.x*dy*dy) - f0.w*dx*dy;
                float ap = f1.y * __expf(fminf(power, 0.0f));
                ap = fminf(ap, 0.99f);
                if (ap >= (1.0f/255.0f)) {
                    float wgt = (T > 1e-4f) ? ap * T : 0.0f;
                    cr += wgt * f1.z;
                    cg += wgt * f1.w;
                    cb += wgt * s_Bc[base + j];
                    T *= (1.0f - ap);
                }
            }
        }
        __syncthreads();
    }

    // ---- ordered composition across the 16 segments ----
    s_col[tid] = make_float4(cr, cg, cb, T);
    __syncthreads();

    if (tid < 64) {
        float Cr = 0.f, Cg = 0.f, Cb = 0.f;
        #pragma unroll
        for (int k = NSEG - 1; k >= 0; k--) {
            float4 a = s_col[k * 64 + sp];
            Cr = a.x + a.w * Cr;
            Cg = a.y + a.w * Cg;
            Cb = a.z + a.w * Cb;
        }
        int pix = (ty0 + (sp >> 3)) * WI + (tx0 + (sp & 7));
        img[0*NPIX + pix] = Cr;
        img[1*NPIX + pix] = Cg;
        img[2*NPIX + pix] = Cb;
    }
}

// ============================================================
extern "C" void kernel_launch(void* const* d_in, const int* in_sizes, int n_in,
                              void* d_out, int out_size)
{
    const float* pws        = (const float*)d_in[0];
    const float* low_shs    = (const float*)d_in[1];
    const float* high_shs   = (const float*)d_in[2];
    const float* alphas_raw = (const float*)d_in[3];
    const float* scales_raw = (const float*)d_in[4];
    const float* rots_raw   = (const float*)d_in[5];
    // d_in[6] = us (unused)
    const float* Rcw        = (const float*)d_in[7];
    const float* tcw        = (const float*)d_in[8];
    const float* cam        = (const float*)d_in[9];

    float* out   = (float*)d_out;
    int write_areas = (out_size >= 3*NPIX + 2*NG) ? 1 : 0;
    float* areas = out + 3*NPIX;

    preprocess_kernel<<<NG/32, 32>>>(pws, low_shs, high_shs, alphas_raw,
                                     scales_raw, rots_raw, Rcw, tcw, cam,
                                     areas, write_areas);
    rank_scatter_kernel<<<NG/32, 1024>>>();
    raster_kernel<<<NTILE, RTHR>>>(out);
}